// round 15
// baseline (speedup 1.0000x reference)
#include <cuda_runtime.h>
#include <cuda_fp16.h>
#include <cstdint>

#define TOK (32*8192)
#define NBATCH 8192
#define HD 128
#define GGRID 304
#define NTILES 4096

// ---------------- scratch ----------------
__device__ __align__(16) __half g_h [(size_t)TOK*HD];    // hidden state, fp16
__device__ __align__(16) __half g_h2[(size_t)TOK*HD];
__device__ __align__(16) __half g_gPh[(size_t)TOK*HD];   // pre-BN G, fp16
__device__ __align__(16) __half g_gQh[(size_t)TOK*HD];
__device__ __align__(16) float g_part[GGRID*256];
__device__ float g_sc[128];
__device__ float g_sh[128];
__device__ unsigned g_ctr;
__device__ __align__(16) __half g_wh[6*128*136];
__device__ __align__(16) __half g_wo[64*136];

// ---------------- helpers ----------------
__device__ __forceinline__ void mma16(float c[4], const uint32_t a[4], const uint32_t b[2]) {
    asm volatile(
        "mma.sync.aligned.m16n8k16.row.col.f32.f16.f16.f32 "
        "{%0,%1,%2,%3},{%4,%5,%6,%7},{%8,%9},{%0,%1,%2,%3};\n"
        : "+f"(c[0]), "+f"(c[1]), "+f"(c[2]), "+f"(c[3])
        : "r"(a[0]), "r"(a[1]), "r"(a[2]), "r"(a[3]), "r"(b[0]), "r"(b[1]));
}
__device__ __forceinline__ uint32_t hadd2u(uint32_t a, uint32_t b) {
    __half2 r = __hadd2(*(__half2*)&a, *(__half2*)&b);
    return *(uint32_t*)&r;
}
__device__ __forceinline__ float wred8(float v) {   // sum over lane strides 16/8/4 (g dim)
    v += __shfl_down_sync(0xffffffffu, v, 16);
    v += __shfl_down_sync(0xffffffffu, v, 8);
    v += __shfl_down_sync(0xffffffffu, v, 4);
    return v;
}

// ---------------- weight prep ----------------
__global__ void wprep_kernel(const float* __restrict__ lw, const float* __restrict__ nw,
                             const float* __restrict__ ow) {
    int bidx = blockIdx.x;
    if (bidx < 6) {
        int m = bidx & 1, l = bidx >> 1;
        const float* src = (m ? nw : lw) + l * 16384;
        __half* dst = g_wh + bidx * (128 * 136);
        for (int idx = threadIdx.x; idx < 16384; idx += 256) {
            int k = idx >> 7, n = idx & 127;
            dst[n * 136 + k] = __float2half_rn(src[idx]);
        }
    } else {
        for (int idx = threadIdx.x; idx < 8192; idx += 256) {
            int k = idx >> 6, n = idx & 63;
            g_wo[n * 136 + k] = __float2half_rn(ow[k * 64 + n]);
        }
    }
}

// ---------------- gconv: persistent, fp16 HMMA, separate S region, shuffle stats ----------------
// smem bytes: Ah [66][136]h @0 (17952) | WLh @17952 (34816) | WNh @52768 (34816)
//             S fp16 [64][136] @87584 (17408) | stats @104992 (4112) -> total 109104
#define GCONV_SMEM 109104

__global__ __launch_bounds__(256, 2) void gconv_kernel(
    const __half* __restrict__ wimg,
    const float* __restrict__ lb, const float* __restrict__ nbb,
    const float* __restrict__ gam, const float* __restrict__ bet,
    const float* __restrict__ mask,
    const float* __restrict__ xin, const float* __restrict__ ew, const float* __restrict__ ebias,
    const __half* __restrict__ hin, const __half* __restrict__ gin,
    __half* __restrict__ hout, __half* __restrict__ gout, int mode)  // 2 = emb layer0, 1 = fused BN
{
    extern __shared__ char smc[];
    __half* Ah  = (__half*)smc;               // logical row lr at smem row lr+1, stride 136
    __half* WLh = (__half*)(smc + 17952);
    __half* WNh = (__half*)(smc + 52768);
    __half* S   = (__half*)(smc + 87584);     // [64][136]
    float* ssum = (float*)(smc + 104992);
    float* ssq  = ssum + 128;
    float* scs  = ssq + 128;
    float* shs  = scs + 128;
    float* ew0  = shs + 128;
    float* ew1  = ew0 + 128;
    float* ebb  = ew1 + 128;
    float* bbv  = ebb + 128;
    float* redflag = bbv + 128;

    const int tid = threadIdx.x;
    const int bid = blockIdx.x;

    if (tid < 128) {
        ssum[tid] = 0.f; ssq[tid] = 0.f;
        scs[tid] = g_sc[tid]; shs[tid] = g_sh[tid];
        ew0[tid] = ew[tid]; ew1[tid] = ew[128 + tid]; ebb[tid] = ebias[tid];
        bbv[tid] = lb[tid] + nbb[tid];
    }
    {
        const uint4* wl4 = (const uint4*)wimg;
        const uint4* wn4 = (const uint4*)(wimg + 128 * 136);
        uint4* WL4 = (uint4*)WLh;
        uint4* WN4 = (uint4*)WNh;
        for (int i = tid; i < 2176; i += 256) {
            WL4[i] = wl4[i];
            WN4[i] = wn4[i];
        }
    }

    const int w = tid >> 5, lane = tid & 31;
    const int g = lane >> 2, t4 = lane & 3;
    const int wm = w & 1, wn = w >> 1;
    const int rbase = wm * 32;
    const int cbN = wn * 32;
    const uint32_t* AhU = (const uint32_t*)Ah;
    const uint32_t* WLU = (const uint32_t*)WLh;
    const uint32_t* WNU = (const uint32_t*)WNh;
    uint32_t* SU = (uint32_t*)S;

    const int lr0 = tid >> 5;                 // row group 0..7
    const int c4  = (tid & 31) << 2;          // fixed channel group

    for (int t = bid; t < NTILES; t += GGRID) {
        const int b = t >> 7;
        const int n_base = (t & 127) << 6;
        const size_t tok0 = (size_t)b * NBATCH + n_base;

        __syncthreads();   // prev tile fully retired (G copy read S; mma read Ah)

        // ---- batched A-tile load (8 exact iters + 64-thread halo), fp16 h ----
        const size_t gbase = (tok0 + lr0) * HD + c4;
        const int nH = (tid < 32) ? ((n_base - 1) & (NBATCH - 1)) : ((n_base + 64) & (NBATCH - 1));
        const size_t tokH = (size_t)b * NBATCH + nH;

        if (mode == 1) {
            uint2 vh[9], vg[9];
            #pragma unroll
            for (int i = 0; i < 8; i++) {
                size_t go = gbase + (size_t)(8 * i) * HD;
                vh[i] = *(const uint2*)(hin + go);
                vg[i] = *(const uint2*)(gin + go);
            }
            if (tid < 64) {
                size_t goH = tokH * HD + c4;
                vh[8] = *(const uint2*)(hin + goH);
                vg[8] = *(const uint2*)(gin + goH);
            }
            #pragma unroll
            for (int i = 0; i < 8; i++) {
                float2 h0 = __half22float2(*(__half2*)&vh[i].x);
                float2 h1 = __half22float2(*(__half2*)&vh[i].y);
                float2 g0 = __half22float2(*(__half2*)&vg[i].x);
                float2 g1 = __half22float2(*(__half2*)&vg[i].y);
                float4 v;
                v.x = h0.x + fmaxf(0.f, g0.x * scs[c4]     + shs[c4]);
                v.y = h0.y + fmaxf(0.f, g0.y * scs[c4 + 1] + shs[c4 + 1]);
                v.z = h1.x + fmaxf(0.f, g1.x * scs[c4 + 2] + shs[c4 + 2]);
                v.w = h1.y + fmaxf(0.f, g1.y * scs[c4 + 3] + shs[c4 + 3]);
                __half2 p0 = __floats2half2_rn(v.x, v.y);
                __half2 p1 = __floats2half2_rn(v.z, v.w);
                uint2 pk; pk.x = *(uint32_t*)&p0; pk.y = *(uint32_t*)&p1;
                *(uint2*)(hout + gbase + (size_t)(8 * i) * HD) = pk;
                *(uint2*)(Ah + (1 + lr0 + 8 * i) * 136 + c4) = pk;
            }
            if (tid < 64) {
                float2 h0 = __half22float2(*(__half2*)&vh[8].x);
                float2 h1 = __half22float2(*(__half2*)&vh[8].y);
                float2 g0 = __half22float2(*(__half2*)&vg[8].x);
                float2 g1 = __half22float2(*(__half2*)&vg[8].y);
                float4 v;
                v.x = h0.x + fmaxf(0.f, g0.x * scs[c4]     + shs[c4]);
                v.y = h0.y + fmaxf(0.f, g0.y * scs[c4 + 1] + shs[c4 + 1]);
                v.z = h1.x + fmaxf(0.f, g1.x * scs[c4 + 2] + shs[c4 + 2]);
                v.w = h1.y + fmaxf(0.f, g1.y * scs[c4 + 3] + shs[c4 + 3]);
                __half2 p0 = __floats2half2_rn(v.x, v.y);
                __half2 p1 = __floats2half2_rn(v.z, v.w);
                uint2 pk; pk.x = *(uint32_t*)&p0; pk.y = *(uint32_t*)&p1;
                int rH = (tid < 32) ? 0 : 65;
                *(uint2*)(Ah + rH * 136 + c4) = pk;
            }
        } else {
            float2 xv[9];
            #pragma unroll
            for (int i = 0; i < 8; i++)
                xv[i] = *(const float2*)(xin + (tok0 + lr0 + 8 * i) * 2);
            if (tid < 64) xv[8] = *(const float2*)(xin + tokH * 2);
            #pragma unroll
            for (int i = 0; i < 8; i++) {
                float x0 = xv[i].x, x1 = xv[i].y;
                float4 v;
                v.x = x0 * ew0[c4]     + x1 * ew1[c4]     + ebb[c4];
                v.y = x0 * ew0[c4 + 1] + x1 * ew1[c4 + 1] + ebb[c4 + 1];
                v.z = x0 * ew0[c4 + 2] + x1 * ew1[c4 + 2] + ebb[c4 + 2];
                v.w = x0 * ew0[c4 + 3] + x1 * ew1[c4 + 3] + ebb[c4 + 3];
                __half2 p0 = __floats2half2_rn(v.x, v.y);
                __half2 p1 = __floats2half2_rn(v.z, v.w);
                uint2 pk; pk.x = *(uint32_t*)&p0; pk.y = *(uint32_t*)&p1;
                *(uint2*)(hout + gbase + (size_t)(8 * i) * HD) = pk;
                *(uint2*)(Ah + (1 + lr0 + 8 * i) * 136 + c4) = pk;
            }
            if (tid < 64) {
                float x0 = xv[8].x, x1 = xv[8].y;
                float4 v;
                v.x = x0 * ew0[c4]     + x1 * ew1[c4]     + ebb[c4];
                v.y = x0 * ew0[c4 + 1] + x1 * ew1[c4 + 1] + ebb[c4 + 1];
                v.z = x0 * ew0[c4 + 2] + x1 * ew1[c4 + 2] + ebb[c4 + 2];
                v.w = x0 * ew0[c4 + 3] + x1 * ew1[c4 + 3] + ebb[c4 + 3];
                __half2 p0 = __floats2half2_rn(v.x, v.y);
                __half2 p1 = __floats2half2_rn(v.z, v.w);
                uint2 pk; pk.x = *(uint32_t*)&p0; pk.y = *(uint32_t*)&p1;
                int rH = (tid < 32) ? 0 : 65;
                *(uint2*)(Ah + rH * 136 + c4) = pk;
            }
        }
        __syncthreads();

        // ---- mainloop: acc = A@WL + A2@WN ----
        float acc[2][4][4];
        #pragma unroll
        for (int i = 0; i < 2; i++)
            #pragma unroll
            for (int j = 0; j < 4; j++)
                #pragma unroll
                for (int q = 0; q < 4; q++) acc[i][j][q] = 0.f;

        #pragma unroll
        for (int ks = 0; ks < 8; ks++) {
            const int k2 = ks * 8;
            uint32_t afr[2][4], a2fr[2][4];
            #pragma unroll
            for (int mt = 0; mt < 2; mt++) {
                int lr = rbase + mt * 16 + g;
                const uint32_t* pc = AhU + (lr + 1) * 68 + k2 + t4;
                afr[mt][0] = pc[0];
                afr[mt][1] = pc[8 * 68];
                afr[mt][2] = pc[4];
                afr[mt][3] = pc[8 * 68 + 4];
                const uint32_t* pl = AhU + lr * 68 + k2 + t4;
                const uint32_t* ph = AhU + (lr + 2) * 68 + k2 + t4;
                a2fr[mt][0] = hadd2u(pl[0],          ph[0]);
                a2fr[mt][1] = hadd2u(pl[8 * 68],     ph[8 * 68]);
                a2fr[mt][2] = hadd2u(pl[4],          ph[4]);
                a2fr[mt][3] = hadd2u(pl[8 * 68 + 4], ph[8 * 68 + 4]);
            }
            uint32_t bL[4][2], bN[4][2];
            #pragma unroll
            for (int nt = 0; nt < 4; nt++) {
                const uint32_t* pL = WLU + (cbN + nt * 8 + g) * 68 + k2 + t4;
                const uint32_t* pN = WNU + (cbN + nt * 8 + g) * 68 + k2 + t4;
                bL[nt][0] = pL[0]; bL[nt][1] = pL[4];
                bN[nt][0] = pN[0]; bN[nt][1] = pN[4];
            }
            #pragma unroll
            for (int mt = 0; mt < 2; mt++)
                #pragma unroll
                for (int nt = 0; nt < 4; nt++) {
                    mma16(acc[mt][nt], afr[mt],  bL[nt]);
                    mma16(acc[mt][nt], a2fr[mt], bN[nt]);
                }
        }

        // ---- epilogue (no sync needed: S region is private until next G copy) ----
        {
            float se[4], sqe[4], so[4], sqo[4];
            #pragma unroll
            for (int nt = 0; nt < 4; nt++) { se[nt]=0.f; sqe[nt]=0.f; so[nt]=0.f; sqo[nt]=0.f; }

            #pragma unroll
            for (int mt = 0; mt < 2; mt++) {
                int r = rbase + mt * 16 + g;
                float m0 = mask[tok0 + r];
                float m1 = mask[tok0 + r + 8];
                #pragma unroll
                for (int nt = 0; nt < 4; nt++) {
                    int c = cbN + nt * 8 + t4 * 2;
                    float b0 = bbv[c], b1 = bbv[c + 1];
                    __half2 v0 = __floats2half2_rn((acc[mt][nt][0] + b0) * m0, (acc[mt][nt][1] + b1) * m0);
                    __half2 v1 = __floats2half2_rn((acc[mt][nt][2] + b0) * m1, (acc[mt][nt][3] + b1) * m1);
                    SU[r * 68 + (c >> 1)]       = *(uint32_t*)&v0;
                    SU[(r + 8) * 68 + (c >> 1)] = *(uint32_t*)&v1;
                    float2 f0 = __half22float2(v0);
                    float2 f1 = __half22float2(v1);
                    se[nt]  += f0.x + f1.x;
                    sqe[nt] += f0.x * f0.x + f1.x * f1.x;
                    so[nt]  += f0.y + f1.y;
                    sqo[nt] += f0.y * f0.y + f1.y * f1.y;
                }
            }
            // reduce over the 8 row-groups (g) within the warp
            #pragma unroll
            for (int nt = 0; nt < 4; nt++) {
                se[nt]  = wred8(se[nt]);
                sqe[nt] = wred8(sqe[nt]);
                so[nt]  = wred8(so[nt]);
                sqo[nt] = wred8(sqo[nt]);
            }
            if (g == 0) {
                #pragma unroll
                for (int nt = 0; nt < 4; nt++) {
                    int c = cbN + nt * 8 + t4 * 2;
                    atomicAdd(&ssum[c],     se[nt]);
                    atomicAdd(&ssq[c],      sqe[nt]);
                    atomicAdd(&ssum[c + 1], so[nt]);
                    atomicAdd(&ssq[c + 1],  sqo[nt]);
                }
            }
        }
        __syncthreads();

        // ---- store G (vectorized from S) ----
        for (int idx = tid; idx < 1024; idx += 256) {
            int r = idx >> 4, qw = idx & 15;
            uint4 v = *(const uint4*)(SU + r * 68 + qw * 4);
            *(uint4*)(gout + (tok0 + r) * HD + qw * 8) = v;
        }
    }
    __syncthreads();
    if (tid < 256) g_part[bid * 256 + tid] = (tid < 128) ? ssum[tid] : ssq[tid - 128];

    // ---- last-CTA BN reduce ----
    __threadfence();
    __syncthreads();
    if (tid == 0) {
        unsigned old = atomicAdd(&g_ctr, 1u);
        redflag[0] = (old == GGRID - 1) ? 1.f : 0.f;
    }
    __syncthreads();
    if (redflag[0] != 0.f) {
        int c = tid & 127, seg = tid >> 7;
        float s = 0.f, q = 0.f;
        for (int i = seg * 152; i < seg * 152 + 152; i++) {
            s += g_part[i * 256 + c];
            q += g_part[i * 256 + 128 + c];
        }
        if (seg == 0) { ssum[c] = s; ssq[c] = q; }
        __syncthreads();
        if (seg == 1) {
            float S2 = ssum[c] + s, Q2 = ssq[c] + q;
            float inv = 1.f / (float)TOK;
            float mean = S2 * inv;
            float var = Q2 * inv - mean * mean;
            float sc = gam[c] * rsqrtf(var + 1e-5f);
            g_sc[c] = sc;
            g_sh[c] = bet[c] - mean * sc;
        }
        if (tid == 0) g_ctr = 0;
    }
}

// ---------------- output head: persistent, fp16 HMMA, fp16 h+G in ----------------
#define OUT_SMEM 55040

__global__ __launch_bounds__(256, 2) void out_kernel(
    const float* __restrict__ b1,
    const float* __restrict__ w2, const float* __restrict__ b2,
    const float* __restrict__ mask, float* __restrict__ out,
    const __half* __restrict__ hin, const __half* __restrict__ gin)
{
    extern __shared__ char smc[];
    __half* Ah  = (__half*)smc;
    __half* W1h = (__half*)(smc + 17408);
    float* S    = (float*)(smc + 34816);
    float* W2s  = (float*)(smc + 53248);
    float* B1s  = (float*)(smc + 53760);
    float* scs  = (float*)(smc + 54016);
    float* shs  = (float*)(smc + 54528);

    const int tid = threadIdx.x, bid = blockIdx.x;

    if (tid < 128) { scs[tid] = g_sc[tid]; shs[tid] = g_sh[tid]; W2s[tid] = w2[tid]; }
    if (tid < 64)  B1s[tid] = b1[tid];
    {
        const uint4* wsrc = (const uint4*)g_wo;
        uint4* wdst = (uint4*)W1h;
        for (int i = tid; i < 1088; i += 256) wdst[i] = wsrc[i];
    }

    const int w = tid >> 5, lane = tid & 31;
    const int g = lane >> 2, t4 = lane & 3;
    const int wm = w & 1, wn = w >> 1;
    const int rbase = wm * 32;
    const int cbN = wn * 16;
    const uint32_t* AU = (const uint32_t*)Ah;
    const uint32_t* WU = (const uint32_t*)W1h;
    const float b2v[2] = { b2[0], b2[1] };

    const int lr0 = tid >> 5;
    const int c4  = (tid & 31) << 2;

    for (int t = bid; t < NTILES; t += GGRID) {
        const size_t tok0 = (size_t)t * 64;

        __syncthreads();

        const size_t gbase = (tok0 + lr0) * HD + c4;
        uint2 vh[8], vg[8];
        #pragma unroll
        for (int i = 0; i < 8; i++) {
            size_t go = gbase + (size_t)(8 * i) * HD;
            vh[i] = *(const uint2*)(hin + go);
            vg[i] = *(const uint2*)(gin + go);
        }
        #pragma unroll
        for (int i = 0; i < 8; i++) {
            float2 h0 = __half22float2(*(__half2*)&vh[i].x);
            float2 h1 = __half22float2(*(__half2*)&vh[i].y);
            float2 g0 = __half22float2(*(__half2*)&vg[i].x);
            float2 g1 = __half22float2(*(__half2*)&vg[i].y);
            float4 hv;
            hv.x = h0.x + fmaxf(0.f, g0.x * scs[c4]     + shs[c4]);
            hv.y = h0.y + fmaxf(0.f, g0.y * scs[c4 + 1] + shs[c4 + 1]);
            hv.z = h1.x + fmaxf(0.f, g1.x * scs[c4 + 2] + shs[c4 + 2]);
            hv.w = h1.y + fmaxf(0.f, g1.y * scs[c4 + 3] + shs[c4 + 3]);
            __half2 p0 = __floats2half2_rn(hv.x, hv.y);
            __half2 p1 = __floats2half2_rn(hv.z, hv.w);
            uint2 pk; pk.x = *(uint32_t*)&p0; pk.y = *(uint32_t*)&p1;
            *(uint2*)(Ah + (lr0 + 8 * i) * 136 + c4) = pk;
        }
        __syncthreads();

        float acc[2][2][4];
        #pragma unroll
        for (int i = 0; i < 2; i++)
            #pragma unroll
            for (int j = 0; j < 2; j++)
                #pragma unroll
                for (int q = 0; q < 4; q++) acc[i][j][q] = 0.f;

        #pragma unroll
        for (int ks = 0; ks < 8; ks++) {
            const int k2 = ks * 8;
            uint32_t afr[2][4];
            #pragma unroll
            for (int mt = 0; mt < 2; mt++) {
                const uint32_t* p = AU + (rbase + mt * 16 + g) * 68 + k2 + t4;
                afr[mt][0] = p[0];
                afr[mt][1] = p[8 * 68];
                afr[mt][2] = p[4];
                afr[mt][3] = p[8 * 68 + 4];
            }
            uint32_t bfr[2][2];
            #pragma unroll
            for (int nt = 0; nt < 2; nt++) {
                const uint32_t* p = WU + (cbN + nt * 8 + g) * 68 + k2 + t4;
                bfr[nt][0] = p[0];
                bfr[nt][1] = p[4];
            }
            #pragma unroll
            for (int mt = 0; mt < 2; mt++)
                #pragma unroll
                for (int nt = 0; nt < 2; nt++)
                    mma16(acc[mt][nt], afr[mt], bfr[nt]);
        }

        #pragma unroll
        for (int mt = 0; mt < 2; mt++)
            #pragma unroll
            for (int nt = 0; nt < 2; nt++) {
                int r = rbase + mt * 16 + g;
                int c = cbN + nt * 8 + t4 * 2;
                S[r * 72 + c]           = fmaxf(0.f, acc[mt][nt][0] + B1s[c]);
                S[r * 72 + c + 1]       = fmaxf(0.f, acc[mt][nt][1] + B1s[c + 1]);
                S[(r + 8) * 72 + c]     = fmaxf(0.f, acc[mt][nt][2] + B1s[c]);
                S[(r + 8) * 72 + c + 1] = fmaxf(0.f, acc[mt][nt][3] + B1s[c + 1]);
            }
        __syncthreads();

        if (tid < 128) {
            int r = tid >> 1, o = tid & 1;
            float s = 0.f;
            #pragma unroll
            for (int j = 0; j < 64; j++) s += S[r * 72 + j] * W2s[j * 2 + o];
            out[(tok0 + r) * 2 + o] = (s + b2v[o]) * mask[tok0 + r];
        }
    }
}

// ---------------- launch ----------------
extern "C" void kernel_launch(void* const* d_in, const int* in_sizes, int n_in,
                              void* d_out, int out_size) {
    const float* x     = (const float*)d_in[0];
    const float* mask  = (const float*)d_in[1];
    const float* emb_w = (const float*)d_in[2];
    const float* emb_b = (const float*)d_in[3];
    const float* lin_w = (const float*)d_in[4];
    const float* lin_b = (const float*)d_in[5];
    const float* nb_w  = (const float*)d_in[6];
    const float* nb_b  = (const float*)d_in[7];
    const float* bn_g  = (const float*)d_in[8];
    const float* bn_b  = (const float*)d_in[9];
    const float* o1w   = (const float*)d_in[10];
    const float* o1b   = (const float*)d_in[11];
    const float* o2w   = (const float*)d_in[12];
    const float* o2b   = (const float*)d_in[13];
    float* out = (float*)d_out;

    __half *hA, *hB, *gPh, *gQh, *wh;
    cudaGetSymbolAddress((void**)&hA, g_h);
    cudaGetSymbolAddress((void**)&hB, g_h2);
    cudaGetSymbolAddress((void**)&gPh, g_gPh);
    cudaGetSymbolAddress((void**)&gQh, g_gQh);
    cudaGetSymbolAddress((void**)&wh, g_wh);

    cudaFuncSetAttribute(gconv_kernel, cudaFuncAttributeMaxDynamicSharedMemorySize, GCONV_SMEM);
    cudaFuncSetAttribute(out_kernel,   cudaFuncAttributeMaxDynamicSharedMemorySize, OUT_SMEM);

    const int WSTR = 128 * 136;

    wprep_kernel<<<7, 256>>>(lin_w, nb_w, o1w);
    gconv_kernel<<<GGRID, 256, GCONV_SMEM>>>(wh + 0 * WSTR, lin_b, nb_b,
                                             bn_g, bn_b, mask,
                                             x, emb_w, emb_b, hA, gPh, hA, gPh, 2);
    gconv_kernel<<<GGRID, 256, GCONV_SMEM>>>(wh + 2 * WSTR, lin_b + 128, nb_b + 128,
                                             bn_g + 128, bn_b + 128, mask,
                                             x, emb_w, emb_b, hA, gPh, hB, gQh, 1);
    gconv_kernel<<<GGRID, 256, GCONV_SMEM>>>(wh + 4 * WSTR, lin_b + 256, nb_b + 256,
                                             bn_g + 256, bn_b + 256, mask,
                                             x, emb_w, emb_b, hB, gQh, hA, gPh, 1);
    out_kernel<<<GGRID, 256, OUT_SMEM>>>(o1b, o2w, o2b, mask, out, hA, gPh);
}

// round 16
// speedup vs baseline: 1.1486x; 1.1486x over previous
#include <cuda_runtime.h>
#include <cuda_fp16.h>
#include <cstdint>

#define TOK (32*8192)
#define NBATCH 8192
#define HD 128
#define GGRID 304
#define NTILES 4096

// ---------------- scratch ----------------
__device__ __align__(16) __half g_h [(size_t)TOK*HD];    // hidden state, fp16
__device__ __align__(16) __half g_h2[(size_t)TOK*HD];
__device__ __align__(16) __half g_gPh[(size_t)TOK*HD];   // pre-BN G, fp16
__device__ __align__(16) __half g_gQh[(size_t)TOK*HD];
__device__ __align__(16) float g_part[GGRID*256];
__device__ float g_sc[128];
__device__ float g_sh[128];
__device__ unsigned g_ctr;
__device__ __align__(16) __half g_wh[6*128*136];
__device__ __align__(16) __half g_wo[64*136];

// ---------------- helpers ----------------
__device__ __forceinline__ void mma16(float c[4], const uint32_t a[4], const uint32_t b[2]) {
    asm volatile(
        "mma.sync.aligned.m16n8k16.row.col.f32.f16.f16.f32 "
        "{%0,%1,%2,%3},{%4,%5,%6,%7},{%8,%9},{%0,%1,%2,%3};\n"
        : "+f"(c[0]), "+f"(c[1]), "+f"(c[2]), "+f"(c[3])
        : "r"(a[0]), "r"(a[1]), "r"(a[2]), "r"(a[3]), "r"(b[0]), "r"(b[1]));
}
__device__ __forceinline__ uint32_t hadd2u(uint32_t a, uint32_t b) {
    __half2 r = __hadd2(*(__half2*)&a, *(__half2*)&b);
    return *(uint32_t*)&r;
}

// ---------------- weight prep ----------------
__global__ void wprep_kernel(const float* __restrict__ lw, const float* __restrict__ nw,
                             const float* __restrict__ ow) {
    int bidx = blockIdx.x;
    if (bidx < 6) {
        int m = bidx & 1, l = bidx >> 1;
        const float* src = (m ? nw : lw) + l * 16384;
        __half* dst = g_wh + bidx * (128 * 136);
        for (int idx = threadIdx.x; idx < 16384; idx += 256) {
            int k = idx >> 7, n = idx & 127;
            dst[n * 136 + k] = __float2half_rn(src[idx]);
        }
    } else {
        for (int idx = threadIdx.x; idx < 8192; idx += 256) {
            int k = idx >> 6, n = idx & 63;
            g_wo[n * 136 + k] = __float2half_rn(ow[k * 64 + n]);
        }
    }
}

// ---------------- gconv: persistent, fp16 HMMA, fp16 h+G streams (R11 schedule) ----------------
// smem bytes: Ah [66][136]h @0 (17952) | WLh @17952 (34816) | WNh @52768 (34816)
//             stats @87584 (4112) -> total 91696
#define GCONV_SMEM 91696

__global__ __launch_bounds__(256, 2) void gconv_kernel(
    const __half* __restrict__ wimg,
    const float* __restrict__ lb, const float* __restrict__ nbb,
    const float* __restrict__ gam, const float* __restrict__ bet,
    const float* __restrict__ mask,
    const float* __restrict__ xin, const float* __restrict__ ew, const float* __restrict__ ebias,
    const __half* __restrict__ hin, const __half* __restrict__ gin,
    __half* __restrict__ hout, __half* __restrict__ gout, int mode)  // 2 = emb layer0, 1 = fused BN
{
    extern __shared__ char smc[];
    __half* Ah  = (__half*)smc;               // logical row lr at smem row lr+1, stride 136
    __half* WLh = (__half*)(smc + 17952);
    __half* WNh = (__half*)(smc + 52768);
    float* ssum = (float*)(smc + 87584);
    float* ssq  = ssum + 128;
    float* scs  = ssq + 128;
    float* shs  = scs + 128;
    float* ew0  = shs + 128;
    float* ew1  = ew0 + 128;
    float* ebb  = ew1 + 128;
    float* bbv  = ebb + 128;
    float* redflag = bbv + 128;
    __half* S   = (__half*)smc;               // epilogue reuse, [64][136]

    const int tid = threadIdx.x;
    const int bid = blockIdx.x;

    if (tid < 128) {
        ssum[tid] = 0.f; ssq[tid] = 0.f;
        scs[tid] = g_sc[tid]; shs[tid] = g_sh[tid];
        ew0[tid] = ew[tid]; ew1[tid] = ew[128 + tid]; ebb[tid] = ebias[tid];
        bbv[tid] = lb[tid] + nbb[tid];
    }
    {
        const uint4* wl4 = (const uint4*)wimg;
        const uint4* wn4 = (const uint4*)(wimg + 128 * 136);
        uint4* WL4 = (uint4*)WLh;
        uint4* WN4 = (uint4*)WNh;
        for (int i = tid; i < 2176; i += 256) {
            WL4[i] = wl4[i];
            WN4[i] = wn4[i];
        }
    }

    const int w = tid >> 5, lane = tid & 31;
    const int g = lane >> 2, t4 = lane & 3;
    const int wm = w & 1, wn = w >> 1;
    const int rbase = wm * 32;
    const int cbN = wn * 32;
    const uint32_t* AhU = (const uint32_t*)Ah;
    const uint32_t* WLU = (const uint32_t*)WLh;
    const uint32_t* WNU = (const uint32_t*)WNh;
    uint32_t* SU = (uint32_t*)S;

    const int lr0 = tid >> 5;                 // row group 0..7
    const int c4  = (tid & 31) << 2;          // fixed channel group

    for (int t = bid; t < NTILES; t += GGRID) {
        const int b = t >> 7;
        const int n_base = (t & 127) << 6;
        const size_t tok0 = (size_t)b * NBATCH + n_base;

        __syncthreads();   // prev tile's S reads done; Ah writable

        // ---- batched A-tile load (8 exact iters + 64-thread halo), fp16 h ----
        const size_t gbase = (tok0 + lr0) * HD + c4;
        const int nH = (tid < 32) ? ((n_base - 1) & (NBATCH - 1)) : ((n_base + 64) & (NBATCH - 1));
        const size_t tokH = (size_t)b * NBATCH + nH;

        if (mode == 1) {
            uint2 vh[9], vg[9];
            #pragma unroll
            for (int i = 0; i < 8; i++) {
                size_t go = gbase + (size_t)(8 * i) * HD;
                vh[i] = *(const uint2*)(hin + go);
                vg[i] = *(const uint2*)(gin + go);
            }
            if (tid < 64) {
                size_t goH = tokH * HD + c4;
                vh[8] = *(const uint2*)(hin + goH);
                vg[8] = *(const uint2*)(gin + goH);
            }
            #pragma unroll
            for (int i = 0; i < 8; i++) {
                float2 h0 = __half22float2(*(__half2*)&vh[i].x);
                float2 h1 = __half22float2(*(__half2*)&vh[i].y);
                float2 g0 = __half22float2(*(__half2*)&vg[i].x);
                float2 g1 = __half22float2(*(__half2*)&vg[i].y);
                float4 v;
                v.x = h0.x + fmaxf(0.f, g0.x * scs[c4]     + shs[c4]);
                v.y = h0.y + fmaxf(0.f, g0.y * scs[c4 + 1] + shs[c4 + 1]);
                v.z = h1.x + fmaxf(0.f, g1.x * scs[c4 + 2] + shs[c4 + 2]);
                v.w = h1.y + fmaxf(0.f, g1.y * scs[c4 + 3] + shs[c4 + 3]);
                __half2 p0 = __floats2half2_rn(v.x, v.y);
                __half2 p1 = __floats2half2_rn(v.z, v.w);
                uint2 pk; pk.x = *(uint32_t*)&p0; pk.y = *(uint32_t*)&p1;
                *(uint2*)(hout + gbase + (size_t)(8 * i) * HD) = pk;
                *(uint2*)(Ah + (1 + lr0 + 8 * i) * 136 + c4) = pk;
            }
            if (tid < 64) {
                float2 h0 = __half22float2(*(__half2*)&vh[8].x);
                float2 h1 = __half22float2(*(__half2*)&vh[8].y);
                float2 g0 = __half22float2(*(__half2*)&vg[8].x);
                float2 g1 = __half22float2(*(__half2*)&vg[8].y);
                float4 v;
                v.x = h0.x + fmaxf(0.f, g0.x * scs[c4]     + shs[c4]);
                v.y = h0.y + fmaxf(0.f, g0.y * scs[c4 + 1] + shs[c4 + 1]);
                v.z = h1.x + fmaxf(0.f, g1.x * scs[c4 + 2] + shs[c4 + 2]);
                v.w = h1.y + fmaxf(0.f, g1.y * scs[c4 + 3] + shs[c4 + 3]);
                __half2 p0 = __floats2half2_rn(v.x, v.y);
                __half2 p1 = __floats2half2_rn(v.z, v.w);
                uint2 pk; pk.x = *(uint32_t*)&p0; pk.y = *(uint32_t*)&p1;
                int rH = (tid < 32) ? 0 : 65;
                *(uint2*)(Ah + rH * 136 + c4) = pk;
            }
        } else {
            float2 xv[9];
            #pragma unroll
            for (int i = 0; i < 8; i++)
                xv[i] = *(const float2*)(xin + (tok0 + lr0 + 8 * i) * 2);
            if (tid < 64) xv[8] = *(const float2*)(xin + tokH * 2);
            #pragma unroll
            for (int i = 0; i < 8; i++) {
                float x0 = xv[i].x, x1 = xv[i].y;
                float4 v;
                v.x = x0 * ew0[c4]     + x1 * ew1[c4]     + ebb[c4];
                v.y = x0 * ew0[c4 + 1] + x1 * ew1[c4 + 1] + ebb[c4 + 1];
                v.z = x0 * ew0[c4 + 2] + x1 * ew1[c4 + 2] + ebb[c4 + 2];
                v.w = x0 * ew0[c4 + 3] + x1 * ew1[c4 + 3] + ebb[c4 + 3];
                __half2 p0 = __floats2half2_rn(v.x, v.y);
                __half2 p1 = __floats2half2_rn(v.z, v.w);
                uint2 pk; pk.x = *(uint32_t*)&p0; pk.y = *(uint32_t*)&p1;
                *(uint2*)(hout + gbase + (size_t)(8 * i) * HD) = pk;
                *(uint2*)(Ah + (1 + lr0 + 8 * i) * 136 + c4) = pk;
            }
            if (tid < 64) {
                float x0 = xv[8].x, x1 = xv[8].y;
                float4 v;
                v.x = x0 * ew0[c4]     + x1 * ew1[c4]     + ebb[c4];
                v.y = x0 * ew0[c4 + 1] + x1 * ew1[c4 + 1] + ebb[c4 + 1];
                v.z = x0 * ew0[c4 + 2] + x1 * ew1[c4 + 2] + ebb[c4 + 2];
                v.w = x0 * ew0[c4 + 3] + x1 * ew1[c4 + 3] + ebb[c4 + 3];
                __half2 p0 = __floats2half2_rn(v.x, v.y);
                __half2 p1 = __floats2half2_rn(v.z, v.w);
                uint2 pk; pk.x = *(uint32_t*)&p0; pk.y = *(uint32_t*)&p1;
                int rH = (tid < 32) ? 0 : 65;
                *(uint2*)(Ah + rH * 136 + c4) = pk;
            }
        }
        __syncthreads();

        // ---- mainloop: acc = A@WL + A2@WN ----
        float acc[2][4][4];
        #pragma unroll
        for (int i = 0; i < 2; i++)
            #pragma unroll
            for (int j = 0; j < 4; j++)
                #pragma unroll
                for (int q = 0; q < 4; q++) acc[i][j][q] = 0.f;

        #pragma unroll
        for (int ks = 0; ks < 8; ks++) {
            const int k2 = ks * 8;
            uint32_t afr[2][4], a2fr[2][4];
            #pragma unroll
            for (int mt = 0; mt < 2; mt++) {
                int lr = rbase + mt * 16 + g;
                const uint32_t* pc = AhU + (lr + 1) * 68 + k2 + t4;
                afr[mt][0] = pc[0];
                afr[mt][1] = pc[8 * 68];
                afr[mt][2] = pc[4];
                afr[mt][3] = pc[8 * 68 + 4];
                const uint32_t* pl = AhU + lr * 68 + k2 + t4;
                const uint32_t* ph = AhU + (lr + 2) * 68 + k2 + t4;
                a2fr[mt][0] = hadd2u(pl[0],          ph[0]);
                a2fr[mt][1] = hadd2u(pl[8 * 68],     ph[8 * 68]);
                a2fr[mt][2] = hadd2u(pl[4],          ph[4]);
                a2fr[mt][3] = hadd2u(pl[8 * 68 + 4], ph[8 * 68 + 4]);
            }
            uint32_t bL[4][2], bN[4][2];
            #pragma unroll
            for (int nt = 0; nt < 4; nt++) {
                const uint32_t* pL = WLU + (cbN + nt * 8 + g) * 68 + k2 + t4;
                const uint32_t* pN = WNU + (cbN + nt * 8 + g) * 68 + k2 + t4;
                bL[nt][0] = pL[0]; bL[nt][1] = pL[4];
                bN[nt][0] = pN[0]; bN[nt][1] = pN[4];
            }
            #pragma unroll
            for (int mt = 0; mt < 2; mt++)
                #pragma unroll
                for (int nt = 0; nt < 4; nt++) {
                    mma16(acc[mt][nt], afr[mt],  bL[nt]);
                    mma16(acc[mt][nt], a2fr[mt], bN[nt]);
                }
        }

        __syncthreads();     // Ah reads done; S (same region) may be written

        // ---- epilogue: bias + mask -> S fp16 ----
        #pragma unroll
        for (int mt = 0; mt < 2; mt++) {
            int r = rbase + mt * 16 + g;
            float m0 = mask[tok0 + r];
            float m1 = mask[tok0 + r + 8];
            #pragma unroll
            for (int nt = 0; nt < 4; nt++) {
                int c = cbN + nt * 8 + t4 * 2;
                float b0 = bbv[c], b1 = bbv[c + 1];
                __half2 v0 = __floats2half2_rn((acc[mt][nt][0] + b0) * m0, (acc[mt][nt][1] + b1) * m0);
                __half2 v1 = __floats2half2_rn((acc[mt][nt][2] + b0) * m1, (acc[mt][nt][3] + b1) * m1);
                SU[r * 68 + (c >> 1)]       = *(uint32_t*)&v0;
                SU[(r + 8) * 68 + (c >> 1)] = *(uint32_t*)&v1;
            }
        }
        __syncthreads();

        // ---- stats + store G ----
        {
            int c = tid & 127, seg = tid >> 7;
            float s = 0.f, q = 0.f;
            #pragma unroll 8
            for (int r = seg * 32; r < seg * 32 + 32; r++) {
                float v = __half2float(S[r * 136 + c]);
                s += v; q += v * v;
            }
            atomicAdd(&ssum[c], s);
            atomicAdd(&ssq[c], q);
        }
        for (int idx = tid; idx < 1024; idx += 256) {
            int r = idx >> 4, qw = idx & 15;
            uint4 v = *(const uint4*)(SU + r * 68 + qw * 4);
            *(uint4*)(gout + (tok0 + r) * HD + qw * 8) = v;
        }
    }
    __syncthreads();
    if (tid < 256) g_part[bid * 256 + tid] = (tid < 128) ? ssum[tid] : ssq[tid - 128];

    // ---- last-CTA BN reduce ----
    __threadfence();
    __syncthreads();
    if (tid == 0) {
        unsigned old = atomicAdd(&g_ctr, 1u);
        redflag[0] = (old == GGRID - 1) ? 1.f : 0.f;
    }
    __syncthreads();
    if (redflag[0] != 0.f) {
        int c = tid & 127, seg = tid >> 7;
        float s = 0.f, q = 0.f;
        for (int i = seg * 152; i < seg * 152 + 152; i++) {
            s += g_part[i * 256 + c];
            q += g_part[i * 256 + 128 + c];
        }
        if (seg == 0) { ssum[c] = s; ssq[c] = q; }
        __syncthreads();
        if (seg == 1) {
            float S2 = ssum[c] + s, Q2 = ssq[c] + q;
            float inv = 1.f / (float)TOK;
            float mean = S2 * inv;
            float var = Q2 * inv - mean * mean;
            float sc = gam[c] * rsqrtf(var + 1e-5f);
            g_sc[c] = sc;
            g_sh[c] = bet[c] - mean * sc;
        }
        if (tid == 0) g_ctr = 0;
    }
}

// ---------------- output head: persistent, fp16 HMMA, fp16 h+G in ----------------
#define OUT_SMEM 55040

__global__ __launch_bounds__(256, 2) void out_kernel(
    const float* __restrict__ b1,
    const float* __restrict__ w2, const float* __restrict__ b2,
    const float* __restrict__ mask, float* __restrict__ out,
    const __half* __restrict__ hin, const __half* __restrict__ gin)
{
    extern __shared__ char smc[];
    __half* Ah  = (__half*)smc;
    __half* W1h = (__half*)(smc + 17408);
    float* S    = (float*)(smc + 34816);
    float* W2s  = (float*)(smc + 53248);
    float* B1s  = (float*)(smc + 53760);
    float* scs  = (float*)(smc + 54016);
    float* shs  = (float*)(smc + 54528);

    const int tid = threadIdx.x, bid = blockIdx.x;

    if (tid < 128) { scs[tid] = g_sc[tid]; shs[tid] = g_sh[tid]; W2s[tid] = w2[tid]; }
    if (tid < 64)  B1s[tid] = b1[tid];
    {
        const uint4* wsrc = (const uint4*)g_wo;
        uint4* wdst = (uint4*)W1h;
        for (int i = tid; i < 1088; i += 256) wdst[i] = wsrc[i];
    }

    const int w = tid >> 5, lane = tid & 31;
    const int g = lane >> 2, t4 = lane & 3;
    const int wm = w & 1, wn = w >> 1;
    const int rbase = wm * 32;
    const int cbN = wn * 16;
    const uint32_t* AU = (const uint32_t*)Ah;
    const uint32_t* WU = (const uint32_t*)W1h;
    const float b2v[2] = { b2[0], b2[1] };

    const int lr0 = tid >> 5;
    const int c4  = (tid & 31) << 2;

    for (int t = bid; t < NTILES; t += GGRID) {
        const size_t tok0 = (size_t)t * 64;

        __syncthreads();

        const size_t gbase = (tok0 + lr0) * HD + c4;
        uint2 vh[8], vg[8];
        #pragma unroll
        for (int i = 0; i < 8; i++) {
            size_t go = gbase + (size_t)(8 * i) * HD;
            vh[i] = *(const uint2*)(hin + go);
            vg[i] = *(const uint2*)(gin + go);
        }
        #pragma unroll
        for (int i = 0; i < 8; i++) {
            float2 h0 = __half22float2(*(__half2*)&vh[i].x);
            float2 h1 = __half22float2(*(__half2*)&vh[i].y);
            float2 g0 = __half22float2(*(__half2*)&vg[i].x);
            float2 g1 = __half22float2(*(__half2*)&vg[i].y);
            float4 hv;
            hv.x = h0.x + fmaxf(0.f, g0.x * scs[c4]     + shs[c4]);
            hv.y = h0.y + fmaxf(0.f, g0.y * scs[c4 + 1] + shs[c4 + 1]);
            hv.z = h1.x + fmaxf(0.f, g1.x * scs[c4 + 2] + shs[c4 + 2]);
            hv.w = h1.y + fmaxf(0.f, g1.y * scs[c4 + 3] + shs[c4 + 3]);
            __half2 p0 = __floats2half2_rn(hv.x, hv.y);
            __half2 p1 = __floats2half2_rn(hv.z, hv.w);
            uint2 pk; pk.x = *(uint32_t*)&p0; pk.y = *(uint32_t*)&p1;
            *(uint2*)(Ah + (lr0 + 8 * i) * 136 + c4) = pk;
        }
        __syncthreads();

        float acc[2][2][4];
        #pragma unroll
        for (int i = 0; i < 2; i++)
            #pragma unroll
            for (int j = 0; j < 2; j++)
                #pragma unroll
                for (int q = 0; q < 4; q++) acc[i][j][q] = 0.f;

        #pragma unroll
        for (int ks = 0; ks < 8; ks++) {
            const int k2 = ks * 8;
            uint32_t afr[2][4];
            #pragma unroll
            for (int mt = 0; mt < 2; mt++) {
                const uint32_t* p = AU + (rbase + mt * 16 + g) * 68 + k2 + t4;
                afr[mt][0] = p[0];
                afr[mt][1] = p[8 * 68];
                afr[mt][2] = p[4];
                afr[mt][3] = p[8 * 68 + 4];
            }
            uint32_t bfr[2][2];
            #pragma unroll
            for (int nt = 0; nt < 2; nt++) {
                const uint32_t* p = WU + (cbN + nt * 8 + g) * 68 + k2 + t4;
                bfr[nt][0] = p[0];
                bfr[nt][1] = p[4];
            }
            #pragma unroll
            for (int mt = 0; mt < 2; mt++)
                #pragma unroll
                for (int nt = 0; nt < 2; nt++)
                    mma16(acc[mt][nt], afr[mt], bfr[nt]);
        }

        #pragma unroll
        for (int mt = 0; mt < 2; mt++)
            #pragma unroll
            for (int nt = 0; nt < 2; nt++) {
                int r = rbase + mt * 16 + g;
                int c = cbN + nt * 8 + t4 * 2;
                S[r * 72 + c]           = fmaxf(0.f, acc[mt][nt][0] + B1s[c]);
                S[r * 72 + c + 1]       = fmaxf(0.f, acc[mt][nt][1] + B1s[c + 1]);
                S[(r + 8) * 72 + c]     = fmaxf(0.f, acc[mt][nt][2] + B1s[c]);
                S[(r + 8) * 72 + c + 1] = fmaxf(0.f, acc[mt][nt][3] + B1s[c + 1]);
            }
        __syncthreads();

        if (tid < 128) {
            int r = tid >> 1, o = tid & 1;
            float s = 0.f;
            #pragma unroll
            for (int j = 0; j < 64; j++) s += S[r * 72 + j] * W2s[j * 2 + o];
            out[(tok0 + r) * 2 + o] = (s + b2v[o]) * mask[tok0 + r];
        }
    }
}

// ---------------- launch ----------------
extern "C" void kernel_launch(void* const* d_in, const int* in_sizes, int n_in,
                              void* d_out, int out_size) {
    const float* x     = (const float*)d_in[0];
    const float* mask  = (const float*)d_in[1];
    const float* emb_w = (const float*)d_in[2];
    const float* emb_b = (const float*)d_in[3];
    const float* lin_w = (const float*)d_in[4];
    const float* lin_b = (const float*)d_in[5];
    const float* nb_w  = (const float*)d_in[6];
    const float* nb_b  = (const float*)d_in[7];
    const float* bn_g  = (const float*)d_in[8];
    const float* bn_b  = (const float*)d_in[9];
    const float* o1w   = (const float*)d_in[10];
    const float* o1b   = (const float*)d_in[11];
    const float* o2w   = (const float*)d_in[12];
    const float* o2b   = (const float*)d_in[13];
    float* out = (float*)d_out;

    __half *hA, *hB, *gPh, *gQh, *wh;
    cudaGetSymbolAddress((void**)&hA, g_h);
    cudaGetSymbolAddress((void**)&hB, g_h2);
    cudaGetSymbolAddress((void**)&gPh, g_gPh);
    cudaGetSymbolAddress((void**)&gQh, g_gQh);
    cudaGetSymbolAddress((void**)&wh, g_wh);

    cudaFuncSetAttribute(gconv_kernel, cudaFuncAttributeMaxDynamicSharedMemorySize, GCONV_SMEM);
    cudaFuncSetAttribute(out_kernel,   cudaFuncAttributeMaxDynamicSharedMemorySize, OUT_SMEM);

    const int WSTR = 128 * 136;

    wprep_kernel<<<7, 256>>>(lin_w, nb_w, o1w);
    gconv_kernel<<<GGRID, 256, GCONV_SMEM>>>(wh + 0 * WSTR, lin_b, nb_b,
                                             bn_g, bn_b, mask,
                                             x, emb_w, emb_b, hA, gPh, hA, gPh, 2);
    gconv_kernel<<<GGRID, 256, GCONV_SMEM>>>(wh + 2 * WSTR, lin_b + 128, nb_b + 128,
                                             bn_g + 128, bn_b + 128, mask,
                                             x, emb_w, emb_b, hA, gPh, hB, gQh, 1);
    gconv_kernel<<<GGRID, 256, GCONV_SMEM>>>(wh + 4 * WSTR, lin_b + 256, nb_b + 256,
                                             bn_g + 256, bn_b + 256, mask,
                                             x, emb_w, emb_b, hB, gQh, hA, gPh, 1);
    out_kernel<<<GGRID, 256, OUT_SMEM>>>(o1b, o2w, o2b, mask, out, hA, gPh);
}

// round 17
// speedup vs baseline: 1.1582x; 1.0084x over previous
#include <cuda_runtime.h>
#include <cuda_fp16.h>
#include <cstdint>

#define TOK (32*8192)
#define NBATCH 8192
#define HD 128
#define GGRID 304
#define NTILES 4096
#define NTILES_OUT 2048

// ---------------- scratch ----------------
__device__ __align__(16) __half g_h [(size_t)TOK*HD];    // hidden state, fp16
__device__ __align__(16) __half g_h2[(size_t)TOK*HD];
__device__ __align__(16) __half g_gPh[(size_t)TOK*HD];   // pre-BN G, fp16
__device__ __align__(16) __half g_gQh[(size_t)TOK*HD];
__device__ __align__(16) float g_part[GGRID*256];
__device__ float g_sc[128];
__device__ float g_sh[128];
__device__ unsigned g_ctr;
__device__ __align__(16) __half g_wh[6*128*136];
__device__ __align__(16) __half g_wo[64*136];

// ---------------- helpers ----------------
__device__ __forceinline__ void mma16(float c[4], const uint32_t a[4], const uint32_t b[2]) {
    asm volatile(
        "mma.sync.aligned.m16n8k16.row.col.f32.f16.f16.f32 "
        "{%0,%1,%2,%3},{%4,%5,%6,%7},{%8,%9},{%0,%1,%2,%3};\n"
        : "+f"(c[0]), "+f"(c[1]), "+f"(c[2]), "+f"(c[3])
        : "r"(a[0]), "r"(a[1]), "r"(a[2]), "r"(a[3]), "r"(b[0]), "r"(b[1]));
}
__device__ __forceinline__ uint32_t hadd2u(uint32_t a, uint32_t b) {
    __half2 r = __hadd2(*(__half2*)&a, *(__half2*)&b);
    return *(uint32_t*)&r;
}

// ---------------- weight prep ----------------
__global__ void wprep_kernel(const float* __restrict__ lw, const float* __restrict__ nw,
                             const float* __restrict__ ow) {
    int bidx = blockIdx.x;
    if (bidx < 6) {
        int m = bidx & 1, l = bidx >> 1;
        const float* src = (m ? nw : lw) + l * 16384;
        __half* dst = g_wh + bidx * (128 * 136);
        for (int idx = threadIdx.x; idx < 16384; idx += 256) {
            int k = idx >> 7, n = idx & 127;
            dst[n * 136 + k] = __float2half_rn(src[idx]);
        }
    } else {
        for (int idx = threadIdx.x; idx < 8192; idx += 256) {
            int k = idx >> 6, n = idx & 63;
            g_wo[n * 136 + k] = __float2half_rn(ow[k * 64 + n]);
        }
    }
}

// ---------------- gconv: persistent, fp16 HMMA, fp16 h+G streams (R14 frozen) ----------------
// smem bytes: Ah [66][136]h @0 (17952) | WLh @17952 (34816) | WNh @52768 (34816)
//             stats @87584 (4112) -> total 91696
#define GCONV_SMEM 91696

__global__ __launch_bounds__(256, 2) void gconv_kernel(
    const __half* __restrict__ wimg,
    const float* __restrict__ lb, const float* __restrict__ nbb,
    const float* __restrict__ gam, const float* __restrict__ bet,
    const float* __restrict__ mask,
    const float* __restrict__ xin, const float* __restrict__ ew, const float* __restrict__ ebias,
    const __half* __restrict__ hin, const __half* __restrict__ gin,
    __half* __restrict__ hout, __half* __restrict__ gout, int mode)  // 2 = emb layer0, 1 = fused BN
{
    extern __shared__ char smc[];
    __half* Ah  = (__half*)smc;               // logical row lr at smem row lr+1, stride 136
    __half* WLh = (__half*)(smc + 17952);
    __half* WNh = (__half*)(smc + 52768);
    float* ssum = (float*)(smc + 87584);
    float* ssq  = ssum + 128;
    float* scs  = ssq + 128;
    float* shs  = scs + 128;
    float* ew0  = shs + 128;
    float* ew1  = ew0 + 128;
    float* ebb  = ew1 + 128;
    float* bbv  = ebb + 128;
    float* redflag = bbv + 128;
    __half* S   = (__half*)smc;               // epilogue reuse, [64][136]

    const int tid = threadIdx.x;
    const int bid = blockIdx.x;

    if (tid < 128) {
        ssum[tid] = 0.f; ssq[tid] = 0.f;
        scs[tid] = g_sc[tid]; shs[tid] = g_sh[tid];
        ew0[tid] = ew[tid]; ew1[tid] = ew[128 + tid]; ebb[tid] = ebias[tid];
        bbv[tid] = lb[tid] + nbb[tid];
    }
    {
        const uint4* wl4 = (const uint4*)wimg;
        const uint4* wn4 = (const uint4*)(wimg + 128 * 136);
        uint4* WL4 = (uint4*)WLh;
        uint4* WN4 = (uint4*)WNh;
        for (int i = tid; i < 2176; i += 256) {
            WL4[i] = wl4[i];
            WN4[i] = wn4[i];
        }
    }

    const int w = tid >> 5, lane = tid & 31;
    const int g = lane >> 2, t4 = lane & 3;
    const int wm = w & 1, wn = w >> 1;
    const int rbase = wm * 32;
    const int cbN = wn * 32;
    const uint32_t* AhU = (const uint32_t*)Ah;
    const uint32_t* WLU = (const uint32_t*)WLh;
    const uint32_t* WNU = (const uint32_t*)WNh;
    uint32_t* SU = (uint32_t*)S;

    const int lr0 = tid >> 5;                 // row group 0..7
    const int c4  = (tid & 31) << 2;          // fixed channel group

    for (int t = bid; t < NTILES; t += GGRID) {
        const int b = t >> 7;
        const int n_base = (t & 127) << 6;
        const size_t tok0 = (size_t)b * NBATCH + n_base;

        __syncthreads();   // prev tile's S reads done; Ah writable

        // ---- batched A-tile load (8 exact iters + 64-thread halo), fp16 h ----
        const size_t gbase = (tok0 + lr0) * HD + c4;
        const int nH = (tid < 32) ? ((n_base - 1) & (NBATCH - 1)) : ((n_base + 64) & (NBATCH - 1));
        const size_t tokH = (size_t)b * NBATCH + nH;

        if (mode == 1) {
            uint2 vh[9], vg[9];
            #pragma unroll
            for (int i = 0; i < 8; i++) {
                size_t go = gbase + (size_t)(8 * i) * HD;
                vh[i] = *(const uint2*)(hin + go);
                vg[i] = *(const uint2*)(gin + go);
            }
            if (tid < 64) {
                size_t goH = tokH * HD + c4;
                vh[8] = *(const uint2*)(hin + goH);
                vg[8] = *(const uint2*)(gin + goH);
            }
            #pragma unroll
            for (int i = 0; i < 8; i++) {
                float2 h0 = __half22float2(*(__half2*)&vh[i].x);
                float2 h1 = __half22float2(*(__half2*)&vh[i].y);
                float2 g0 = __half22float2(*(__half2*)&vg[i].x);
                float2 g1 = __half22float2(*(__half2*)&vg[i].y);
                float4 v;
                v.x = h0.x + fmaxf(0.f, g0.x * scs[c4]     + shs[c4]);
                v.y = h0.y + fmaxf(0.f, g0.y * scs[c4 + 1] + shs[c4 + 1]);
                v.z = h1.x + fmaxf(0.f, g1.x * scs[c4 + 2] + shs[c4 + 2]);
                v.w = h1.y + fmaxf(0.f, g1.y * scs[c4 + 3] + shs[c4 + 3]);
                __half2 p0 = __floats2half2_rn(v.x, v.y);
                __half2 p1 = __floats2half2_rn(v.z, v.w);
                uint2 pk; pk.x = *(uint32_t*)&p0; pk.y = *(uint32_t*)&p1;
                *(uint2*)(hout + gbase + (size_t)(8 * i) * HD) = pk;
                *(uint2*)(Ah + (1 + lr0 + 8 * i) * 136 + c4) = pk;
            }
            if (tid < 64) {
                float2 h0 = __half22float2(*(__half2*)&vh[8].x);
                float2 h1 = __half22float2(*(__half2*)&vh[8].y);
                float2 g0 = __half22float2(*(__half2*)&vg[8].x);
                float2 g1 = __half22float2(*(__half2*)&vg[8].y);
                float4 v;
                v.x = h0.x + fmaxf(0.f, g0.x * scs[c4]     + shs[c4]);
                v.y = h0.y + fmaxf(0.f, g0.y * scs[c4 + 1] + shs[c4 + 1]);
                v.z = h1.x + fmaxf(0.f, g1.x * scs[c4 + 2] + shs[c4 + 2]);
                v.w = h1.y + fmaxf(0.f, g1.y * scs[c4 + 3] + shs[c4 + 3]);
                __half2 p0 = __floats2half2_rn(v.x, v.y);
                __half2 p1 = __floats2half2_rn(v.z, v.w);
                uint2 pk; pk.x = *(uint32_t*)&p0; pk.y = *(uint32_t*)&p1;
                int rH = (tid < 32) ? 0 : 65;
                *(uint2*)(Ah + rH * 136 + c4) = pk;
            }
        } else {
            float2 xv[9];
            #pragma unroll
            for (int i = 0; i < 8; i++)
                xv[i] = *(const float2*)(xin + (tok0 + lr0 + 8 * i) * 2);
            if (tid < 64) xv[8] = *(const float2*)(xin + tokH * 2);
            #pragma unroll
            for (int i = 0; i < 8; i++) {
                float x0 = xv[i].x, x1 = xv[i].y;
                float4 v;
                v.x = x0 * ew0[c4]     + x1 * ew1[c4]     + ebb[c4];
                v.y = x0 * ew0[c4 + 1] + x1 * ew1[c4 + 1] + ebb[c4 + 1];
                v.z = x0 * ew0[c4 + 2] + x1 * ew1[c4 + 2] + ebb[c4 + 2];
                v.w = x0 * ew0[c4 + 3] + x1 * ew1[c4 + 3] + ebb[c4 + 3];
                __half2 p0 = __floats2half2_rn(v.x, v.y);
                __half2 p1 = __floats2half2_rn(v.z, v.w);
                uint2 pk; pk.x = *(uint32_t*)&p0; pk.y = *(uint32_t*)&p1;
                *(uint2*)(hout + gbase + (size_t)(8 * i) * HD) = pk;
                *(uint2*)(Ah + (1 + lr0 + 8 * i) * 136 + c4) = pk;
            }
            if (tid < 64) {
                float x0 = xv[8].x, x1 = xv[8].y;
                float4 v;
                v.x = x0 * ew0[c4]     + x1 * ew1[c4]     + ebb[c4];
                v.y = x0 * ew0[c4 + 1] + x1 * ew1[c4 + 1] + ebb[c4 + 1];
                v.z = x0 * ew0[c4 + 2] + x1 * ew1[c4 + 2] + ebb[c4 + 2];
                v.w = x0 * ew0[c4 + 3] + x1 * ew1[c4 + 3] + ebb[c4 + 3];
                __half2 p0 = __floats2half2_rn(v.x, v.y);
                __half2 p1 = __floats2half2_rn(v.z, v.w);
                uint2 pk; pk.x = *(uint32_t*)&p0; pk.y = *(uint32_t*)&p1;
                int rH = (tid < 32) ? 0 : 65;
                *(uint2*)(Ah + rH * 136 + c4) = pk;
            }
        }
        __syncthreads();

        // ---- mainloop: acc = A@WL + A2@WN ----
        float acc[2][4][4];
        #pragma unroll
        for (int i = 0; i < 2; i++)
            #pragma unroll
            for (int j = 0; j < 4; j++)
                #pragma unroll
                for (int q = 0; q < 4; q++) acc[i][j][q] = 0.f;

        #pragma unroll
        for (int ks = 0; ks < 8; ks++) {
            const int k2 = ks * 8;
            uint32_t afr[2][4], a2fr[2][4];
            #pragma unroll
            for (int mt = 0; mt < 2; mt++) {
                int lr = rbase + mt * 16 + g;
                const uint32_t* pc = AhU + (lr + 1) * 68 + k2 + t4;
                afr[mt][0] = pc[0];
                afr[mt][1] = pc[8 * 68];
                afr[mt][2] = pc[4];
                afr[mt][3] = pc[8 * 68 + 4];
                const uint32_t* pl = AhU + lr * 68 + k2 + t4;
                const uint32_t* ph = AhU + (lr + 2) * 68 + k2 + t4;
                a2fr[mt][0] = hadd2u(pl[0],          ph[0]);
                a2fr[mt][1] = hadd2u(pl[8 * 68],     ph[8 * 68]);
                a2fr[mt][2] = hadd2u(pl[4],          ph[4]);
                a2fr[mt][3] = hadd2u(pl[8 * 68 + 4], ph[8 * 68 + 4]);
            }
            uint32_t bL[4][2], bN[4][2];
            #pragma unroll
            for (int nt = 0; nt < 4; nt++) {
                const uint32_t* pL = WLU + (cbN + nt * 8 + g) * 68 + k2 + t4;
                const uint32_t* pN = WNU + (cbN + nt * 8 + g) * 68 + k2 + t4;
                bL[nt][0] = pL[0]; bL[nt][1] = pL[4];
                bN[nt][0] = pN[0]; bN[nt][1] = pN[4];
            }
            #pragma unroll
            for (int mt = 0; mt < 2; mt++)
                #pragma unroll
                for (int nt = 0; nt < 4; nt++) {
                    mma16(acc[mt][nt], afr[mt],  bL[nt]);
                    mma16(acc[mt][nt], a2fr[mt], bN[nt]);
                }
        }

        __syncthreads();     // Ah reads done; S (same region) may be written

        // ---- epilogue: bias + mask -> S fp16 ----
        #pragma unroll
        for (int mt = 0; mt < 2; mt++) {
            int r = rbase + mt * 16 + g;
            float m0 = mask[tok0 + r];
            float m1 = mask[tok0 + r + 8];
            #pragma unroll
            for (int nt = 0; nt < 4; nt++) {
                int c = cbN + nt * 8 + t4 * 2;
                float b0 = bbv[c], b1 = bbv[c + 1];
                __half2 v0 = __floats2half2_rn((acc[mt][nt][0] + b0) * m0, (acc[mt][nt][1] + b1) * m0);
                __half2 v1 = __floats2half2_rn((acc[mt][nt][2] + b0) * m1, (acc[mt][nt][3] + b1) * m1);
                SU[r * 68 + (c >> 1)]       = *(uint32_t*)&v0;
                SU[(r + 8) * 68 + (c >> 1)] = *(uint32_t*)&v1;
            }
        }
        __syncthreads();

        // ---- stats + store G ----
        {
            int c = tid & 127, seg = tid >> 7;
            float s = 0.f, q = 0.f;
            #pragma unroll 8
            for (int r = seg * 32; r < seg * 32 + 32; r++) {
                float v = __half2float(S[r * 136 + c]);
                s += v; q += v * v;
            }
            atomicAdd(&ssum[c], s);
            atomicAdd(&ssq[c], q);
        }
        for (int idx = tid; idx < 1024; idx += 256) {
            int r = idx >> 4, qw = idx & 15;
            uint4 v = *(const uint4*)(SU + r * 68 + qw * 4);
            *(uint4*)(gout + (tok0 + r) * HD + qw * 8) = v;
        }
    }
    __syncthreads();
    if (tid < 256) g_part[bid * 256 + tid] = (tid < 128) ? ssum[tid] : ssq[tid - 128];

    // ---- last-CTA BN reduce ----
    __threadfence();
    __syncthreads();
    if (tid == 0) {
        unsigned old = atomicAdd(&g_ctr, 1u);
        redflag[0] = (old == GGRID - 1) ? 1.f : 0.f;
    }
    __syncthreads();
    if (redflag[0] != 0.f) {
        int c = tid & 127, seg = tid >> 7;
        float s = 0.f, q = 0.f;
        for (int i = seg * 152; i < seg * 152 + 152; i++) {
            s += g_part[i * 256 + c];
            q += g_part[i * 256 + 128 + c];
        }
        if (seg == 0) { ssum[c] = s; ssq[c] = q; }
        __syncthreads();
        if (seg == 1) {
            float S2 = ssum[c] + s, Q2 = ssq[c] + q;
            float inv = 1.f / (float)TOK;
            float mean = S2 * inv;
            float var = Q2 * inv - mean * mean;
            float sc = gam[c] * rsqrtf(var + 1e-5f);
            g_sc[c] = sc;
            g_sh[c] = bet[c] - mean * sc;
        }
        if (tid == 0) g_ctr = 0;
    }
}

// ---------------- output head: persistent, fp16 HMMA, 128-row tiles, padded S ----------------
// smem bytes: Ah [128][136]h @0 (34816) | W1h @34816 (17408) | S f32 [128][77] @52224 (39424)
//             W2s @91648 (512) | B1s @92160 (256) | scs @92416 (512) | shs @92928 (512) -> 93440
#define OUT_SMEM 93440

__global__ __launch_bounds__(256, 2) void out_kernel(
    const float* __restrict__ b1,
    const float* __restrict__ w2, const float* __restrict__ b2,
    const float* __restrict__ mask, float* __restrict__ out,
    const __half* __restrict__ hin, const __half* __restrict__ gin)
{
    extern __shared__ char smc[];
    __half* Ah  = (__half*)smc;
    __half* W1h = (__half*)(smc + 34816);
    float* S    = (float*)(smc + 52224);   // [128][77]
    float* W2s  = (float*)(smc + 91648);
    float* B1s  = (float*)(smc + 92160);
    float* scs  = (float*)(smc + 92416);
    float* shs  = (float*)(smc + 92928);

    const int tid = threadIdx.x, bid = blockIdx.x;

    if (tid < 128) { scs[tid] = g_sc[tid]; shs[tid] = g_sh[tid]; W2s[tid] = w2[tid]; }
    if (tid < 64)  B1s[tid] = b1[tid];
    {
        const uint4* wsrc = (const uint4*)g_wo;
        uint4* wdst = (uint4*)W1h;
        for (int i = tid; i < 1088; i += 256) wdst[i] = wsrc[i];
    }

    const int w = tid >> 5, lane = tid & 31;
    const int g = lane >> 2, t4 = lane & 3;
    const int wm = w & 3, wn = w >> 2;       // 4 m x 2 n warp grid over 128x64
    const int rbase = wm * 32;
    const int cbN = wn * 32;
    const uint32_t* AU = (const uint32_t*)Ah;
    const uint32_t* WU = (const uint32_t*)W1h;
    const float b2v[2] = { b2[0], b2[1] };

    const int lr0 = tid >> 5;
    const int c4  = (tid & 31) << 2;

    for (int t = bid; t < NTILES_OUT; t += GGRID) {
        const size_t tok0 = (size_t)t * 128;

        __syncthreads();   // prev tile's S reads (GEMV) done; Ah writable

        // ---- batched loads: 16 rows per thread ----
        const size_t gbase = (tok0 + lr0) * HD + c4;
        uint2 vh[16], vg[16];
        #pragma unroll
        for (int i = 0; i < 16; i++) {
            size_t go = gbase + (size_t)(8 * i) * HD;
            vh[i] = *(const uint2*)(hin + go);
            vg[i] = *(const uint2*)(gin + go);
        }
        #pragma unroll
        for (int i = 0; i < 16; i++) {
            float2 h0 = __half22float2(*(__half2*)&vh[i].x);
            float2 h1 = __half22float2(*(__half2*)&vh[i].y);
            float2 g0 = __half22float2(*(__half2*)&vg[i].x);
            float2 g1 = __half22float2(*(__half2*)&vg[i].y);
            float4 hv;
            hv.x = h0.x + fmaxf(0.f, g0.x * scs[c4]     + shs[c4]);
            hv.y = h0.y + fmaxf(0.f, g0.y * scs[c4 + 1] + shs[c4 + 1]);
            hv.z = h1.x + fmaxf(0.f, g1.x * scs[c4 + 2] + shs[c4 + 2]);
            hv.w = h1.y + fmaxf(0.f, g1.y * scs[c4 + 3] + shs[c4 + 3]);
            __half2 p0 = __floats2half2_rn(hv.x, hv.y);
            __half2 p1 = __floats2half2_rn(hv.z, hv.w);
            uint2 pk; pk.x = *(uint32_t*)&p0; pk.y = *(uint32_t*)&p1;
            *(uint2*)(Ah + (lr0 + 8 * i) * 136 + c4) = pk;
        }
        __syncthreads();

        // ---- mma: [128x64] = A[128x128] @ W1^T ----
        float acc[2][4][4];
        #pragma unroll
        for (int i = 0; i < 2; i++)
            #pragma unroll
            for (int j = 0; j < 4; j++)
                #pragma unroll
                for (int q = 0; q < 4; q++) acc[i][j][q] = 0.f;

        #pragma unroll
        for (int ks = 0; ks < 8; ks++) {
            const int k2 = ks * 8;
            uint32_t afr[2][4];
            #pragma unroll
            for (int mt = 0; mt < 2; mt++) {
                const uint32_t* p = AU + (rbase + mt * 16 + g) * 68 + k2 + t4;
                afr[mt][0] = p[0];
                afr[mt][1] = p[8 * 68];
                afr[mt][2] = p[4];
                afr[mt][3] = p[8 * 68 + 4];
            }
            uint32_t bfr[4][2];
            #pragma unroll
            for (int nt = 0; nt < 4; nt++) {
                const uint32_t* p = WU + (cbN + nt * 8 + g) * 68 + k2 + t4;
                bfr[nt][0] = p[0];
                bfr[nt][1] = p[4];
            }
            #pragma unroll
            for (int mt = 0; mt < 2; mt++)
                #pragma unroll
                for (int nt = 0; nt < 4; nt++)
                    mma16(acc[mt][nt], afr[mt], bfr[nt]);
        }

        // ---- S = relu(acc + b1), stride 77 (separate region, no sync needed) ----
        #pragma unroll
        for (int mt = 0; mt < 2; mt++)
            #pragma unroll
            for (int nt = 0; nt < 4; nt++) {
                int r = rbase + mt * 16 + g;
                int c = cbN + nt * 8 + t4 * 2;
                S[r * 77 + c]           = fmaxf(0.f, acc[mt][nt][0] + B1s[c]);
                S[r * 77 + c + 1]       = fmaxf(0.f, acc[mt][nt][1] + B1s[c + 1]);
                S[(r + 8) * 77 + c]     = fmaxf(0.f, acc[mt][nt][2] + B1s[c]);
                S[(r + 8) * 77 + c + 1] = fmaxf(0.f, acc[mt][nt][3] + B1s[c + 1]);
            }
        __syncthreads();

        // ---- GEMV: all 256 threads, conflict-free stride 77 ----
        {
            int r = tid >> 1, o = tid & 1;
            float s = 0.f;
            #pragma unroll
            for (int j = 0; j < 64; j++) s += S[r * 77 + j] * W2s[j * 2 + o];
            out[(tok0 + r) * 2 + o] = (s + b2v[o]) * mask[tok0 + r];
        }
    }
}

// ---------------- launch ----------------
extern "C" void kernel_launch(void* const* d_in, const int* in_sizes, int n_in,
                              void* d_out, int out_size) {
    const float* x     = (const float*)d_in[0];
    const float* mask  = (const float*)d_in[1];
    const float* emb_w = (const float*)d_in[2];
    const float* emb_b = (const float*)d_in[3];
    const float* lin_w = (const float*)d_in[4];
    const float* lin_b = (const float*)d_in[5];
    const float* nb_w  = (const float*)d_in[6];
    const float* nb_b  = (const float*)d_in[7];
    const float* bn_g  = (const float*)d_in[8];
    const float* bn_b  = (const float*)d_in[9];
    const float* o1w   = (const float*)d_in[10];
    const float* o1b   = (const float*)d_in[11];
    const float* o2w   = (const float*)d_in[12];
    const float* o2b   = (const float*)d_in[13];
    float* out = (float*)d_out;

    __half *hA, *hB, *gPh, *gQh, *wh;
    cudaGetSymbolAddress((void**)&hA, g_h);
    cudaGetSymbolAddress((void**)&hB, g_h2);
    cudaGetSymbolAddress((void**)&gPh, g_gPh);
    cudaGetSymbolAddress((void**)&gQh, g_gQh);
    cudaGetSymbolAddress((void**)&wh, g_wh);

    cudaFuncSetAttribute(gconv_kernel, cudaFuncAttributeMaxDynamicSharedMemorySize, GCONV_SMEM);
    cudaFuncSetAttribute(out_kernel,   cudaFuncAttributeMaxDynamicSharedMemorySize, OUT_SMEM);

    const int WSTR = 128 * 136;

    wprep_kernel<<<7, 256>>>(lin_w, nb_w, o1w);
    gconv_kernel<<<GGRID, 256, GCONV_SMEM>>>(wh + 0 * WSTR, lin_b, nb_b,
                                             bn_g, bn_b, mask,
                                             x, emb_w, emb_b, hA, gPh, hA, gPh, 2);
    gconv_kernel<<<GGRID, 256, GCONV_SMEM>>>(wh + 2 * WSTR, lin_b + 128, nb_b + 128,
                                             bn_g + 128, bn_b + 128, mask,
                                             x, emb_w, emb_b, hA, gPh, hB, gQh, 1);
    gconv_kernel<<<GGRID, 256, GCONV_SMEM>>>(wh + 4 * WSTR, lin_b + 256, nb_b + 256,
                                             bn_g + 256, bn_b + 256, mask,
                                             x, emb_w, emb_b, hB, gQh, hA, gPh, 1);
    out_kernel<<<GGRID, 256, OUT_SMEM>>>(o1b, o2w, o2b, mask, out, hA, gPh);
}